// round 12
// baseline (speedup 1.0000x reference)
#include <cuda_runtime.h>
#include <cuda_bf16.h>

#define LDIM 4096
#define BDIM 32
#define CIN  64
#define ODIM 128
#define KDIM 9
#define CCHUNKS 2               // split-K chunks over channel dim
#define CPER   (CIN / CCHUNKS)  // 32 channels per chunk
#define OCHUNK 32               // outputs per main-kernel block (z=4)

typedef unsigned long long u64;

// Scratch (allocation-free rule: __device__ globals)
__device__ float g_part[CCHUNKS * BDIM * LDIM]; // partial channel sums, 1 MB
__device__ u64   g_wp[ODIM * 5 * 2];            // {w,w}x9,{bias,bias} as u64x2 rows
__device__ float g_evinv;                       // 1 / ||err_vector||

// Constant bank: per o, 5 ulonglong2 = {{w0,w0},{w1,w1}} .. {{w8,w8},{b,b}}
// -> 5 LDC.128 per output channel, zero packing instructions in the o-loop.
__constant__ ulonglong2 c_wp[ODIM * 5];         // 10 KB

// ---- packed f32x2 helpers ----
__device__ __forceinline__ u64 pack2(float lo, float hi) {
    u64 r; asm("mov.b64 %0, {%1,%2};" : "=l"(r) : "f"(lo), "f"(hi)); return r;
}
__device__ __forceinline__ u64 ffma2(u64 a, u64 b, u64 c) {
    u64 d; asm("fma.rn.f32x2 %0, %1, %2, %3;" : "=l"(d) : "l"(a), "l"(b), "l"(c));
    return d;
}
__device__ __forceinline__ float2 unpack2(u64 v) {
    float2 f; asm("mov.b64 {%0,%1}, %2;" : "=f"(f.x), "=f"(f.y) : "l"(v)); return f;
}

// ---------------------------------------------------------------------------
// Kernel A: split-K channel reduction (512 blocks x 128 thr) + prep (block 512)
// ---------------------------------------------------------------------------
__global__ __launch_bounds__(128) void reduce_prep_kernel(
    const float* __restrict__ x,
    const float* __restrict__ wc,
    const float* __restrict__ ev,
    const float* __restrict__ bias) {

    const int bx = blockIdx.x;
    const int t  = threadIdx.x;

    if (bx < BDIM * 16) {                      // 512 reduce blocks
        const int b   = bx >> 4;               // 0..31
        const int sub = bx & 15;
        const int lt  = sub >> 1;              // l-tile 0..7 (128 float4 each)
        const int cc  = sub & 1;               // channel chunk 0..1
        const int l4  = lt * 128 + t;          // 0..1023

        const float4* xp = reinterpret_cast<const float4*>(x) +
                           ((size_t)b * CIN + cc * CPER) * (LDIM / 4) + l4;
        float4 a0 = make_float4(0.f, 0.f, 0.f, 0.f);
        float4 a1 = make_float4(0.f, 0.f, 0.f, 0.f);
#pragma unroll 8
        for (int i = 0; i < CPER; i += 2) {
            float4 v0 = __ldg(xp + (i    ) * (LDIM / 4));
            float4 v1 = __ldg(xp + (i + 1) * (LDIM / 4));
            a0.x += v0.x; a0.y += v0.y; a0.z += v0.z; a0.w += v0.w;
            a1.x += v1.x; a1.y += v1.y; a1.z += v1.z; a1.w += v1.w;
        }
        a0.x += a1.x; a0.y += a1.y; a0.z += a1.z; a0.w += a1.w;
        reinterpret_cast<float4*>(g_part)[(cc * BDIM + b) * (LDIM / 4) + l4] = a0;
        return;
    }

    // ---- prep block (128 threads) ----
    __shared__ float red[128];
    float ssq = 0.f;
    for (int i = t; i < LDIM; i += 128) { float v = ev[i]; ssq += v * v; }
    red[t] = ssq;
    __syncthreads();
    for (int s = 64; s > 0; s >>= 1) {
        if (t < s) red[t] += red[t + s];
        __syncthreads();
    }
    if (t == 0) g_evinv = rsqrtf(red[0]);

    // one thread per output channel; write pre-duplicated {w,w} u64 rows
    {
        float w[KDIM];
        float n = 0.f;
#pragma unroll
        for (int k = 0; k < KDIM; ++k) { w[k] = wc[t * KDIM + k]; n += w[k] * w[k]; }
        float inv = rsqrtf(n);
#pragma unroll
        for (int k = 0; k < KDIM; ++k) {
            float wn = w[k] * inv;
            g_wp[t * 10 + k] = pack2(wn, wn);
        }
        g_wp[t * 10 + 9] = pack2(bias[t], bias[t]);
    }
}

// ---------------------------------------------------------------------------
// Kernel B: out[b,o,l] = ev[l]/||ev|| * sum_k w[o,k]*xs[b, idx[k,l]] + bias[o]
// grid: (4 l-tiles of 1024, 32 b, 4 o-chunks of 32) = 512 blocks x 256 thr
// => 4096 warps (occ ~43%). lpt=4 as two f32x2 accumulators. Weights come
// pre-duplicated from the constant bank: 5 LDC.128 + 18 FFMA2 + 1 STG.128
// per output channel — no packing instructions in the loop.
// ---------------------------------------------------------------------------
__global__ __launch_bounds__(256, 3) void gmconv_main_kernel(
    const int*   __restrict__ idxm,
    const float* __restrict__ ev,
    float*       __restrict__ out) {

    __shared__ float s_xs[LDIM];                    // 16 KB (only smem)

    const int tile  = blockIdx.x;                   // 0..3
    const int b     = blockIdx.y;                   // 0..31
    const int obase = blockIdx.z * OCHUNK;          // 0,32,64,96
    const int t     = threadIdx.x;

    // stage xs[b] = p0 + p1 (L2-resident partials)
    {
        float4* s4 = reinterpret_cast<float4*>(s_xs);
        const float4* g4 = reinterpret_cast<const float4*>(g_part);
#pragma unroll
        for (int i = t; i < LDIM / 4; i += 256) {
            float4 p0 = __ldg(&g4[(0 * BDIM + b) * (LDIM / 4) + i]);
            float4 p1 = __ldg(&g4[(1 * BDIM + b) * (LDIM / 4) + i]);
            s4[i] = make_float4(p0.x + p1.x, p0.y + p1.y,
                                p0.z + p1.z, p0.w + p1.w);
        }
    }
    __syncthreads();

    const int l = tile * 1024 + t * 4;
    const float evinv = g_evinv;
    float4 e4 = __ldg(reinterpret_cast<const float4*>(ev + l));
    const float ex = e4.x * evinv, ey = e4.y * evinv,
                ez = e4.z * evinv, ew = e4.w * evinv;

    // gather 9 neighbor quads from smem, pre-scaled, packed into f32x2 pairs
    u64 g01[KDIM], g23[KDIM];
#pragma unroll
    for (int k = 0; k < KDIM; ++k) {
        int4 id = __ldg(reinterpret_cast<const int4*>(idxm + k * LDIM + l));
        g01[k] = pack2(s_xs[id.x] * ex, s_xs[id.y] * ey);
        g23[k] = pack2(s_xs[id.z] * ez, s_xs[id.w] * ew);
    }

    float* outp = out + ((size_t)b * ODIM + obase) * LDIM + l;
#pragma unroll 4
    for (int o = 0; o < OCHUNK; ++o) {
        const ulonglong2* wp = &c_wp[(obase + o) * 5];
        const ulonglong2 p0 = wp[0];   // {w0,w0},{w1,w1}
        const ulonglong2 p1 = wp[1];   // {w2,w2},{w3,w3}
        const ulonglong2 p2 = wp[2];   // {w4,w4},{w5,w5}
        const ulonglong2 p3 = wp[3];   // {w6,w6},{w7,w7}
        const ulonglong2 p4 = wp[4];   // {w8,w8},{bias,bias}

        u64 acc01 = p4.y, acc23 = p4.y;
        acc01 = ffma2(p0.x, g01[0], acc01);  acc23 = ffma2(p0.x, g23[0], acc23);
        acc01 = ffma2(p0.y, g01[1], acc01);  acc23 = ffma2(p0.y, g23[1], acc23);
        acc01 = ffma2(p1.x, g01[2], acc01);  acc23 = ffma2(p1.x, g23[2], acc23);
        acc01 = ffma2(p1.y, g01[3], acc01);  acc23 = ffma2(p1.y, g23[3], acc23);
        acc01 = ffma2(p2.x, g01[4], acc01);  acc23 = ffma2(p2.x, g23[4], acc23);
        acc01 = ffma2(p2.y, g01[5], acc01);  acc23 = ffma2(p2.y, g23[5], acc23);
        acc01 = ffma2(p3.x, g01[6], acc01);  acc23 = ffma2(p3.x, g23[6], acc23);
        acc01 = ffma2(p3.y, g01[7], acc01);  acc23 = ffma2(p3.y, g23[7], acc23);
        acc01 = ffma2(p4.x, g01[8], acc01);  acc23 = ffma2(p4.x, g23[8], acc23);

        float2 r01 = unpack2(acc01);
        float2 r23 = unpack2(acc23);
        __stcs(reinterpret_cast<float4*>(outp + (size_t)o * LDIM),
               make_float4(r01.x, r01.y, r23.x, r23.y));   // streaming STG.128
    }
}

// ---------------------------------------------------------------------------
extern "C" void kernel_launch(void* const* d_in, const int* in_sizes, int n_in,
                              void* d_out, int out_size) {
    const float* x    = nullptr;
    const float* wc   = nullptr;
    const float* ev   = nullptr;
    const float* bias = nullptr;
    const int*   idxm = nullptr;

    for (int i = 0; i < n_in; ++i) {
        switch (in_sizes[i]) {
            case BDIM * CIN * LDIM: x    = (const float*)d_in[i]; break;  // 8388608
            case ODIM * KDIM:       wc   = (const float*)d_in[i]; break;  // 1152
            case LDIM:              ev   = (const float*)d_in[i]; break;  // 4096
            case ODIM:              bias = (const float*)d_in[i]; break;  // 128
            case KDIM * LDIM:       idxm = (const int*)  d_in[i]; break;  // 36864
            default: break;
        }
    }

    float* out = (float*)d_out;

    reduce_prep_kernel<<<BDIM * 16 + 1, 128>>>(x, wc, ev, bias);

    // ONE graph-capturable D2D memcpy node: packed weights+bias -> const bank
    void* wsrc = nullptr;
    cudaGetSymbolAddress(&wsrc, g_wp);
    cudaMemcpyToSymbolAsync(c_wp, wsrc, ODIM * 5 * sizeof(ulonglong2), 0,
                            cudaMemcpyDeviceToDevice, 0);

    gmconv_main_kernel<<<dim3(4, BDIM, 4), 256>>>(idxm, ev, out);
}

// round 13
// speedup vs baseline: 1.0888x; 1.0888x over previous
#include <cuda_runtime.h>
#include <cuda_bf16.h>

#define LDIM 4096
#define BDIM 32
#define CIN  64
#define ODIM 128
#define KDIM 9
#define CCHUNKS 2               // split-K chunks over channel dim
#define CPER   (CIN / CCHUNKS)  // 32 channels per chunk
#define OCHUNK 64               // outputs per main-kernel block
#define WSTRIDE 12              // padded row: w0..w8, bias, 0, 0

typedef unsigned long long u64;

// Scratch (allocation-free rule: __device__ globals)
__device__ float g_part[CCHUNKS * BDIM * LDIM]; // partial channel sums, 1 MB
__device__ float g_wb[ODIM * WSTRIDE];          // padded normalized w + bias
__device__ float g_evinv;                       // 1 / ||err_vector||

// Constant bank: padded rows viewed as float4 (3 per o) -> 3x LDC.128 per o
__constant__ float4 c_wb4[ODIM * 3];            // 6 KB

// ---- packed f32x2 helpers ----
__device__ __forceinline__ u64 pack2(float lo, float hi) {
    u64 r; asm("mov.b64 %0, {%1,%2};" : "=l"(r) : "f"(lo), "f"(hi)); return r;
}
__device__ __forceinline__ u64 ffma2(u64 a, u64 b, u64 c) {
    u64 d; asm("fma.rn.f32x2 %0, %1, %2, %3;" : "=l"(d) : "l"(a), "l"(b), "l"(c));
    return d;
}
__device__ __forceinline__ u64 add2(u64 a, u64 b) {
    u64 d; asm("add.rn.f32x2 %0, %1, %2;" : "=l"(d) : "l"(a), "l"(b));
    return d;
}
__device__ __forceinline__ float2 unpack2(u64 v) {
    float2 f; asm("mov.b64 {%0,%1}, %2;" : "=f"(f.x), "=f"(f.y) : "l"(v)); return f;
}

// ---------------------------------------------------------------------------
// Kernel A: split-K channel reduction (512 blocks x 128 thr) + prep (block 512)
// ---------------------------------------------------------------------------
__global__ __launch_bounds__(128) void reduce_prep_kernel(
    const float* __restrict__ x,
    const float* __restrict__ wc,
    const float* __restrict__ ev,
    const float* __restrict__ bias) {

    const int bx = blockIdx.x;
    const int t  = threadIdx.x;

    if (bx < BDIM * 16) {                      // 512 reduce blocks
        const int b   = bx >> 4;               // 0..31
        const int sub = bx & 15;
        const int lt  = sub >> 1;              // l-tile 0..7 (128 float4 each)
        const int cc  = sub & 1;               // channel chunk 0..1
        const int l4  = lt * 128 + t;          // 0..1023

        const float4* xp = reinterpret_cast<const float4*>(x) +
                           ((size_t)b * CIN + cc * CPER) * (LDIM / 4) + l4;
        float4 a0 = make_float4(0.f, 0.f, 0.f, 0.f);
        float4 a1 = make_float4(0.f, 0.f, 0.f, 0.f);
#pragma unroll 8
        for (int i = 0; i < CPER; i += 2) {
            float4 v0 = __ldg(xp + (i    ) * (LDIM / 4));
            float4 v1 = __ldg(xp + (i + 1) * (LDIM / 4));
            a0.x += v0.x; a0.y += v0.y; a0.z += v0.z; a0.w += v0.w;
            a1.x += v1.x; a1.y += v1.y; a1.z += v1.z; a1.w += v1.w;
        }
        a0.x += a1.x; a0.y += a1.y; a0.z += a1.z; a0.w += a1.w;
        reinterpret_cast<float4*>(g_part)[(cc * BDIM + b) * (LDIM / 4) + l4] = a0;
        return;
    }

    // ---- prep block (128 threads) ----
    __shared__ float red[128];
    float ssq = 0.f;
    for (int i = t; i < LDIM; i += 128) { float v = ev[i]; ssq += v * v; }
    red[t] = ssq;
    __syncthreads();
    for (int s = 64; s > 0; s >>= 1) {
        if (t < s) red[t] += red[t + s];
        __syncthreads();
    }
    if (t == 0) g_evinv = rsqrtf(red[0]);

    // one thread per output channel (128 threads = ODIM); padded 12-row
    {
        float w[KDIM];
        float n = 0.f;
#pragma unroll
        for (int k = 0; k < KDIM; ++k) { w[k] = wc[t * KDIM + k]; n += w[k] * w[k]; }
        float inv = rsqrtf(n);
#pragma unroll
        for (int k = 0; k < KDIM; ++k) g_wb[t * WSTRIDE + k] = w[k] * inv;
        g_wb[t * WSTRIDE + 9]  = bias[t];
        g_wb[t * WSTRIDE + 10] = 0.f;
        g_wb[t * WSTRIDE + 11] = 0.f;
    }
}

// ---------------------------------------------------------------------------
// Kernel B: out[b,o,l] = ev[l]/||ev|| * sum_k w[o,k]*xs[b, idx[k,l]] + bias[o]
// grid: (4 l-tiles of 1024, 32 b, 2 o-chunks of 64) = 256 blocks x 256 thr.
// lpt=4 as two f32x2 lane-pairs; per o the k-sum is SPLIT into two chains
// (k0..4 with bias, k5..8 from zero) -> 4 independent FFMA2 chains of depth
// 5/4 instead of 2 chains of depth 9. Weights via 3x LDC.128 per o.
// ---------------------------------------------------------------------------
__global__ __launch_bounds__(256, 2) void gmconv_main_kernel(
    const int*   __restrict__ idxm,
    const float* __restrict__ ev,
    float*       __restrict__ out) {

    __shared__ float s_xs[LDIM];                    // 16 KB (only smem)

    const int tile  = blockIdx.x;                   // 0..3
    const int b     = blockIdx.y;                   // 0..31
    const int obase = blockIdx.z * OCHUNK;          // 0, 64
    const int t     = threadIdx.x;

    // stage xs[b] = p0 + p1 (L2-resident partials)
    {
        float4* s4 = reinterpret_cast<float4*>(s_xs);
        const float4* g4 = reinterpret_cast<const float4*>(g_part);
#pragma unroll
        for (int i = t; i < LDIM / 4; i += 256) {
            float4 p0 = __ldg(&g4[(0 * BDIM + b) * (LDIM / 4) + i]);
            float4 p1 = __ldg(&g4[(1 * BDIM + b) * (LDIM / 4) + i]);
            s4[i] = make_float4(p0.x + p1.x, p0.y + p1.y,
                                p0.z + p1.z, p0.w + p1.w);
        }
    }
    __syncthreads();

    const int l = tile * 1024 + t * 4;
    const float evinv = g_evinv;
    float4 e4 = __ldg(reinterpret_cast<const float4*>(ev + l));
    const float ex = e4.x * evinv, ey = e4.y * evinv,
                ez = e4.z * evinv, ew = e4.w * evinv;

    // gather 9 neighbor quads from smem, pre-scaled, packed into f32x2 pairs
    u64 g01[KDIM], g23[KDIM];
#pragma unroll
    for (int k = 0; k < KDIM; ++k) {
        int4 id = __ldg(reinterpret_cast<const int4*>(idxm + k * LDIM + l));
        g01[k] = pack2(s_xs[id.x] * ex, s_xs[id.y] * ey);
        g23[k] = pack2(s_xs[id.z] * ez, s_xs[id.w] * ew);
    }

    const u64 zero2 = 0;                            // {0.f, 0.f}
    float* outp = out + ((size_t)b * ODIM + obase) * LDIM + l;

#pragma unroll 4
    for (int o = 0; o < OCHUNK; ++o) {
        // 3x LDC.128: w0..w3 | w4..w7 | w8, bias, 0, 0
        const float4 wa = c_wb4[(obase + o) * 3 + 0];
        const float4 wb = c_wb4[(obase + o) * 3 + 1];
        const float4 wc = c_wb4[(obase + o) * 3 + 2];

        const u64 w0 = pack2(wa.x, wa.x), w1 = pack2(wa.y, wa.y);
        const u64 w2 = pack2(wa.z, wa.z), w3 = pack2(wa.w, wa.w);
        const u64 w4 = pack2(wb.x, wb.x), w5 = pack2(wb.y, wb.y);
        const u64 w6 = pack2(wb.z, wb.z), w7 = pack2(wb.w, wb.w);
        const u64 w8 = pack2(wc.x, wc.x);
        const u64 bb = pack2(wc.y, wc.y);

        // chain A: k = 0..4 (seeded with bias); chain B: k = 5..8 (from zero)
        u64 a01 = bb,    a23 = bb;
        u64 b01 = zero2, b23 = zero2;

        a01 = ffma2(w0, g01[0], a01);  a23 = ffma2(w0, g23[0], a23);
        b01 = ffma2(w5, g01[5], b01);  b23 = ffma2(w5, g23[5], b23);
        a01 = ffma2(w1, g01[1], a01);  a23 = ffma2(w1, g23[1], a23);
        b01 = ffma2(w6, g01[6], b01);  b23 = ffma2(w6, g23[6], b23);
        a01 = ffma2(w2, g01[2], a01);  a23 = ffma2(w2, g23[2], a23);
        b01 = ffma2(w7, g01[7], b01);  b23 = ffma2(w7, g23[7], b23);
        a01 = ffma2(w3, g01[3], a01);  a23 = ffma2(w3, g23[3], a23);
        b01 = ffma2(w8, g01[8], b01);  b23 = ffma2(w8, g23[8], b23);
        a01 = ffma2(w4, g01[4], a01);  a23 = ffma2(w4, g23[4], a23);

        const u64 acc01 = add2(a01, b01);
        const u64 acc23 = add2(a23, b23);

        float2 r01 = unpack2(acc01);
        float2 r23 = unpack2(acc23);
        __stcs(reinterpret_cast<float4*>(outp + (size_t)o * LDIM),
               make_float4(r01.x, r01.y, r23.x, r23.y));   // streaming STG.128
    }
}

// ---------------------------------------------------------------------------
extern "C" void kernel_launch(void* const* d_in, const int* in_sizes, int n_in,
                              void* d_out, int out_size) {
    const float* x    = nullptr;
    const float* wc   = nullptr;
    const float* ev   = nullptr;
    const float* bias = nullptr;
    const int*   idxm = nullptr;

    for (int i = 0; i < n_in; ++i) {
        switch (in_sizes[i]) {
            case BDIM * CIN * LDIM: x    = (const float*)d_in[i]; break;  // 8388608
            case ODIM * KDIM:       wc   = (const float*)d_in[i]; break;  // 1152
            case LDIM:              ev   = (const float*)d_in[i]; break;  // 4096
            case ODIM:              bias = (const float*)d_in[i]; break;  // 128
            case KDIM * LDIM:       idxm = (const int*)  d_in[i]; break;  // 36864
            default: break;
        }
    }

    float* out = (float*)d_out;

    reduce_prep_kernel<<<BDIM * 16 + 1, 128>>>(x, wc, ev, bias);

    // ONE graph-capturable D2D memcpy node: padded weights+bias -> const bank
    void* wsrc = nullptr;
    cudaGetSymbolAddress(&wsrc, g_wb);
    cudaMemcpyToSymbolAsync(c_wb4, wsrc, ODIM * WSTRIDE * sizeof(float), 0,
                            cudaMemcpyDeviceToDevice, 0);

    gmconv_main_kernel<<<dim3(4, BDIM, 2), 256>>>(idxm, ev, out);
}